// round 1
// baseline (speedup 1.0000x reference)
#include <cuda_runtime.h>
#include <cuda_bf16.h>
#include <cstdint>

// Problem constants (fixed by the dataset)
#define NROWS 1048576
#define DIM   128
#define NSEG  4096

// Scratch (allocation-free rule: __device__ globals)
__device__ float g_xs[NSEG * DIM];              // segment sums   (2 MB)
__device__ float g_xm[NSEG * DIM];              // xs @ Lambda^T  (2 MB)
__device__ __nv_bfloat16 g_Gb[DIM * DIM];       // Gamma_W in bf16 (32 KB)

// ---------------------------------------------------------------------------
// Kernel 0: zero g_xs, convert Gamma_W -> bf16
// grid 2048 x 256  (covers NSEG*DIM = 524288)
// ---------------------------------------------------------------------------
__global__ void k0_init(const float* __restrict__ GW) {
    int idx = blockIdx.x * blockDim.x + threadIdx.x;
    if (idx < NSEG * DIM) g_xs[idx] = 0.0f;
    if (idx < DIM * DIM)  g_Gb[idx] = __float2bfloat16(GW[idx]);
}

// ---------------------------------------------------------------------------
// Kernel 1: segment sum over sorted seg_ids.
// 256 threads = 8 row-streams of 32 lanes; each lane owns 4 columns (float4).
// Run-length accumulate in registers, atomicAdd only at segment boundaries.
// grid = NROWS / 1024 = 1024 blocks, 1024 rows/block, 128 iters/stream.
// ---------------------------------------------------------------------------
__global__ __launch_bounds__(256) void k1_segsum(const float* __restrict__ x,
                                                 const int* __restrict__ seg) {
    int t = threadIdx.x;
    int stream = t >> 5;              // 0..7
    int c = (t & 31) * 4;             // column base
    int base = blockIdx.x * 1024 + stream;

    float4 acc = make_float4(0.f, 0.f, 0.f, 0.f);
    int cur = seg[base];

    #pragma unroll 4
    for (int i = 0; i < 128; i++) {
        int r = base + i * 8;
        int s = seg[r];
        float4 v = *(const float4*)(x + (size_t)r * DIM + c);
        if (s != cur) {
            float* d = g_xs + (size_t)cur * DIM + c;
            atomicAdd(d + 0, acc.x); atomicAdd(d + 1, acc.y);
            atomicAdd(d + 2, acc.z); atomicAdd(d + 3, acc.w);
            acc = make_float4(0.f, 0.f, 0.f, 0.f);
            cur = s;
        }
        acc.x += v.x; acc.y += v.y; acc.z += v.z; acc.w += v.w;
    }
    float* d = g_xs + (size_t)cur * DIM + c;
    atomicAdd(d + 0, acc.x); atomicAdd(d + 1, acc.y);
    atomicAdd(d + 2, acc.z); atomicAdd(d + 3, acc.w);
}

// ---------------------------------------------------------------------------
// Kernel 2: g_xm = g_xs @ Lambda_W^T   (fp32 exact; xm dominates |out|)
// 128 threads, 16 seg-rows per block, Lambda transposed into smem.
// grid = NSEG/16 = 256.  Dynamic smem: Lt[128][129] + xs[16][128] = 74240 B.
// ---------------------------------------------------------------------------
__global__ __launch_bounds__(128) void k2_xm(const float* __restrict__ LW) {
    extern __shared__ float sm2[];
    float* Lt  = sm2;                 // [128][129], Lt[k][j] = LW[j][k]
    float* xss = sm2 + 128 * 129;     // [16][128]
    int t = threadIdx.x;
    int R0 = blockIdx.x * 16;

    for (int i = 0; i < 128; i++) {
        int e = i * 128 + t;
        int j = e >> 7, k = e & 127;
        Lt[k * 129 + j] = LW[e];
    }
    for (int i = 0; i < 16; i++) {
        int e = i * 128 + t;
        int r = e >> 7, k = e & 127;
        xss[r * 128 + k] = g_xs[(size_t)(R0 + r) * DIM + k];
    }
    __syncthreads();

    int j = t;
    float acc[16];
    #pragma unroll
    for (int r = 0; r < 16; r++) acc[r] = 0.f;

    for (int k = 0; k < 128; k++) {
        float lv = Lt[k * 129 + j];
        #pragma unroll
        for (int r = 0; r < 16; r++) acc[r] += xss[r * 128 + k] * lv;
    }
    #pragma unroll
    for (int r = 0; r < 16; r++)
        g_xm[(size_t)(R0 + r) * DIM + j] = acc[r];
}

// ---------------------------------------------------------------------------
// Kernel 3: out = x @ Gamma^T (bf16 HMMA) + bias - xm[seg]
// Block tile: 128 rows x 128 cols, 256 threads (8 warps, warp = 16 rows).
// mma.sync.m16n8k16 row.col: A = x tile (row-major), B = Gamma stored [n][k]
// (i.e. B^T row-major == B col-major). Fragments loaded with plain LDS.32
// (stride 136 halves -> provably conflict-free: bank = (4g+t)%32, all distinct).
// ---------------------------------------------------------------------------
#define ASTRIDE 136
#define K3_SMEM (2 * 128 * ASTRIDE * 2)   // 69632 bytes

__global__ __launch_bounds__(256, 2) void k3_main(const float* __restrict__ x,
                                                  const int* __restrict__ seg,
                                                  const float* __restrict__ bias,
                                                  float* __restrict__ out) {
    extern __shared__ __nv_bfloat16 sm3[];
    __nv_bfloat16* As = sm3;                       // [128][136]
    __nv_bfloat16* Bs = sm3 + 128 * ASTRIDE;       // [128][136]  Bs[n][k]=Gamma[n][k]

    int tid = threadIdx.x;
    int r0 = blockIdx.x * 128;

    // Load x tile -> bf16 As (coalesced float4 loads)
    #pragma unroll
    for (int i = 0; i < 16; i++) {
        int e = i * 1024 + tid * 4;       // < 16384
        int r = e >> 7, c = e & 127;
        float4 v = *(const float4*)(x + (size_t)(r0 + r) * DIM + c);
        __nv_bfloat162* dst = (__nv_bfloat162*)(As + r * ASTRIDE + c);
        dst[0] = __floats2bfloat162_rn(v.x, v.y);
        dst[1] = __floats2bfloat162_rn(v.z, v.w);
    }
    // Load Gamma (pre-converted bf16) -> Bs (16B vector copies)
    #pragma unroll
    for (int i = 0; i < 8; i++) {
        int e = i * 2048 + tid * 8;       // < 16384
        int r = e >> 7, c = e & 127;
        *(uint4*)(Bs + r * ASTRIDE + c) = *(const uint4*)(g_Gb + e);
    }
    __syncthreads();

    int warp = tid >> 5;
    int lane = tid & 31;
    int g = lane >> 2;                 // 0..7
    int t4 = lane & 3;                 // 0..3
    int m0 = warp * 16;

    // Preload all A fragments (8 k-steps x 4 regs)
    const __nv_bfloat16* Ab = As + (m0 + g) * ASTRIDE + 2 * t4;
    uint32_t a[8][4];
    #pragma unroll
    for (int ks = 0; ks < 8; ks++) {
        int o = ks * 16;
        a[ks][0] = *(const uint32_t*)(Ab + o);
        a[ks][1] = *(const uint32_t*)(Ab + o + 8 * ASTRIDE);
        a[ks][2] = *(const uint32_t*)(Ab + o + 8);
        a[ks][3] = *(const uint32_t*)(Ab + o + 8 * ASTRIDE + 8);
    }

    float acc[16][4];
    #pragma unroll
    for (int nt = 0; nt < 16; nt++)
        #pragma unroll
        for (int q = 0; q < 4; q++) acc[nt][q] = 0.f;

    #pragma unroll
    for (int nt = 0; nt < 16; nt++) {
        const __nv_bfloat16* Bb = Bs + (nt * 8 + g) * ASTRIDE + 2 * t4;
        #pragma unroll
        for (int ks = 0; ks < 8; ks++) {
            uint32_t b0 = *(const uint32_t*)(Bb + ks * 16);
            uint32_t b1 = *(const uint32_t*)(Bb + ks * 16 + 8);
            asm volatile(
                "mma.sync.aligned.m16n8k16.row.col.f32.bf16.bf16.f32 "
                "{%0,%1,%2,%3}, {%4,%5,%6,%7}, {%8,%9}, {%0,%1,%2,%3};\n"
                : "+f"(acc[nt][0]), "+f"(acc[nt][1]),
                  "+f"(acc[nt][2]), "+f"(acc[nt][3])
                : "r"(a[ks][0]), "r"(a[ks][1]), "r"(a[ks][2]), "r"(a[ks][3]),
                  "r"(b0), "r"(b1));
        }
    }

    // Epilogue: + bias - xm[seg]; sector-aligned float2 stores
    int ra = r0 + m0 + g;
    int rb = ra + 8;
    int sa = seg[ra];
    int sb = seg[rb];
    const float* xa = g_xm + (size_t)sa * DIM;
    const float* xb = g_xm + (size_t)sb * DIM;

    #pragma unroll
    for (int nt = 0; nt < 16; nt++) {
        int j = nt * 8 + 2 * t4;
        float2 bb = *(const float2*)(bias + j);
        float2 ma = *(const float2*)(xa + j);
        float2 mb = *(const float2*)(xb + j);
        float2 oa, ob;
        oa.x = acc[nt][0] + bb.x - ma.x;
        oa.y = acc[nt][1] + bb.y - ma.y;
        ob.x = acc[nt][2] + bb.x - mb.x;
        ob.y = acc[nt][3] + bb.y - mb.y;
        *(float2*)(out + (size_t)ra * DIM + j) = oa;
        *(float2*)(out + (size_t)rb * DIM + j) = ob;
    }
}

// ---------------------------------------------------------------------------
extern "C" void kernel_launch(void* const* d_in, const int* in_sizes, int n_in,
                              void* d_out, int out_size) {
    const float* x   = (const float*)d_in[0];
    const int*   seg = (const int*)d_in[1];
    // Robustly locate Gamma_W (16384), Gamma_b (128), Lambda_W (16384)
    const float* GW = nullptr;
    const float* Gb = nullptr;
    const float* LW = nullptr;
    for (int i = 2; i < n_in; i++) {
        int s = in_sizes[i];
        if (s == DIM * DIM) { if (!GW) GW = (const float*)d_in[i]; else LW = (const float*)d_in[i]; }
        else if (s == DIM) { Gb = (const float*)d_in[i]; }
    }
    float* out = (float*)d_out;

    cudaFuncSetAttribute(k2_xm,   cudaFuncAttributeMaxDynamicSharedMemorySize, 74240);
    cudaFuncSetAttribute(k3_main, cudaFuncAttributeMaxDynamicSharedMemorySize, K3_SMEM);

    k0_init<<<2048, 256>>>(GW);
    k1_segsum<<<NROWS / 1024, 256>>>(x, seg);
    k2_xm<<<NSEG / 16, 128, 74240>>>(LW);
    k3_main<<<NROWS / 128, 256, K3_SMEM>>>(x, seg, Gb, out);
}

// round 2
// speedup vs baseline: 1.0055x; 1.0055x over previous
#include <cuda_runtime.h>
#include <cuda_bf16.h>
#include <cstdint>

// Problem constants (fixed by the dataset)
#define NROWS 1048576
#define DIM   128
#define NSEG  4096

// Scratch (allocation-free rule: __device__ globals)
__device__ float g_xs[NSEG * DIM];              // segment sums   (2 MB)
__device__ float g_xm[NSEG * DIM];              // xs @ Lambda^T  (2 MB)
__device__ __nv_bfloat16 g_Gb[DIM * DIM];       // Gamma_W in bf16 (32 KB)

// ---------------------------------------------------------------------------
// Kernel 0: zero g_xs, convert Gamma_W -> bf16
// grid 2048 x 256  (covers NSEG*DIM = 524288)
// ---------------------------------------------------------------------------
__global__ void k0_init(const float* __restrict__ GW) {
    int idx = blockIdx.x * blockDim.x + threadIdx.x;
    if (idx < NSEG * DIM) g_xs[idx] = 0.0f;
    if (idx < DIM * DIM)  g_Gb[idx] = __float2bfloat16(GW[idx]);
}

// ---------------------------------------------------------------------------
// Kernel 1: segment sum over sorted seg_ids.
// 256 threads = 8 row-streams of 32 lanes; each lane owns 4 columns (float4).
// Run-length accumulate in registers, atomicAdd only at segment boundaries.
// grid = NROWS / 1024 = 1024 blocks, 1024 rows/block, 128 iters/stream.
// ---------------------------------------------------------------------------
__global__ __launch_bounds__(256) void k1_segsum(const float* __restrict__ x,
                                                 const int* __restrict__ seg) {
    int t = threadIdx.x;
    int stream = t >> 5;              // 0..7
    int c = (t & 31) * 4;             // column base
    int base = blockIdx.x * 1024 + stream;

    float4 acc = make_float4(0.f, 0.f, 0.f, 0.f);
    int cur = seg[base];

    #pragma unroll 4
    for (int i = 0; i < 128; i++) {
        int r = base + i * 8;
        int s = seg[r];
        float4 v = *(const float4*)(x + (size_t)r * DIM + c);
        if (s != cur) {
            float* d = g_xs + (size_t)cur * DIM + c;
            atomicAdd(d + 0, acc.x); atomicAdd(d + 1, acc.y);
            atomicAdd(d + 2, acc.z); atomicAdd(d + 3, acc.w);
            acc = make_float4(0.f, 0.f, 0.f, 0.f);
            cur = s;
        }
        acc.x += v.x; acc.y += v.y; acc.z += v.z; acc.w += v.w;
    }
    float* d = g_xs + (size_t)cur * DIM + c;
    atomicAdd(d + 0, acc.x); atomicAdd(d + 1, acc.y);
    atomicAdd(d + 2, acc.z); atomicAdd(d + 3, acc.w);
}

// ---------------------------------------------------------------------------
// Kernel 2: g_xm = g_xs @ Lambda_W^T   (fp32 exact; xm dominates |out|)
// 128 threads, 16 seg-rows per block, Lambda transposed into smem.
// grid = NSEG/16 = 256.  Dynamic smem: Lt[128][129] + xs[16][128] = 74240 B.
// ---------------------------------------------------------------------------
__global__ __launch_bounds__(128) void k2_xm(const float* __restrict__ LW) {
    extern __shared__ float sm2[];
    float* Lt  = sm2;                 // [128][129], Lt[k][j] = LW[j][k]
    float* xss = sm2 + 128 * 129;     // [16][128]
    int t = threadIdx.x;
    int R0 = blockIdx.x * 16;

    for (int i = 0; i < 128; i++) {
        int e = i * 128 + t;
        int j = e >> 7, k = e & 127;
        Lt[k * 129 + j] = LW[e];
    }
    for (int i = 0; i < 16; i++) {
        int e = i * 128 + t;
        int r = e >> 7, k = e & 127;
        xss[r * 128 + k] = g_xs[(size_t)(R0 + r) * DIM + k];
    }
    __syncthreads();

    int j = t;
    float acc[16];
    #pragma unroll
    for (int r = 0; r < 16; r++) acc[r] = 0.f;

    for (int k = 0; k < 128; k++) {
        float lv = Lt[k * 129 + j];
        #pragma unroll
        for (int r = 0; r < 16; r++) acc[r] += xss[r * 128 + k] * lv;
    }
    #pragma unroll
    for (int r = 0; r < 16; r++)
        g_xm[(size_t)(R0 + r) * DIM + j] = acc[r];
}

// ---------------------------------------------------------------------------
// Kernel 3: out = x @ Gamma^T (bf16 HMMA) + bias - xm[seg]
// Block tile: 128 rows x 128 cols, 256 threads (8 warps, warp = 16 rows).
// mma.sync.m16n8k16 row.col: A = x tile (row-major), B = Gamma stored [n][k]
// (i.e. B^T row-major == B col-major). Fragments loaded with plain LDS.32
// (stride 136 halves -> provably conflict-free: bank = (4g+t)%32, all distinct).
// ---------------------------------------------------------------------------
#define ASTRIDE 136
#define K3_SMEM (2 * 128 * ASTRIDE * 2)   // 69632 bytes

__global__ __launch_bounds__(256, 2) void k3_main(const float* __restrict__ x,
                                                  const int* __restrict__ seg,
                                                  const float* __restrict__ bias,
                                                  float* __restrict__ out) {
    extern __shared__ __nv_bfloat16 sm3[];
    __nv_bfloat16* As = sm3;                       // [128][136]
    __nv_bfloat16* Bs = sm3 + 128 * ASTRIDE;       // [128][136]  Bs[n][k]=Gamma[n][k]

    int tid = threadIdx.x;
    int r0 = blockIdx.x * 128;

    // Load x tile -> bf16 As (coalesced float4 loads)
    #pragma unroll
    for (int i = 0; i < 16; i++) {
        int e = i * 1024 + tid * 4;       // < 16384
        int r = e >> 7, c = e & 127;
        float4 v = *(const float4*)(x + (size_t)(r0 + r) * DIM + c);
        __nv_bfloat162* dst = (__nv_bfloat162*)(As + r * ASTRIDE + c);
        dst[0] = __floats2bfloat162_rn(v.x, v.y);
        dst[1] = __floats2bfloat162_rn(v.z, v.w);
    }
    // Load Gamma (pre-converted bf16) -> Bs (16B vector copies)
    #pragma unroll
    for (int i = 0; i < 8; i++) {
        int e = i * 2048 + tid * 8;       // < 16384
        int r = e >> 7, c = e & 127;
        *(uint4*)(Bs + r * ASTRIDE + c) = *(const uint4*)(g_Gb + e);
    }
    __syncthreads();

    int warp = tid >> 5;
    int lane = tid & 31;
    int g = lane >> 2;                 // 0..7
    int t4 = lane & 3;                 // 0..3
    int m0 = warp * 16;

    // Preload all A fragments (8 k-steps x 4 regs)
    const __nv_bfloat16* Ab = As + (m0 + g) * ASTRIDE + 2 * t4;
    uint32_t a[8][4];
    #pragma unroll
    for (int ks = 0; ks < 8; ks++) {
        int o = ks * 16;
        a[ks][0] = *(const uint32_t*)(Ab + o);
        a[ks][1] = *(const uint32_t*)(Ab + o + 8 * ASTRIDE);
        a[ks][2] = *(const uint32_t*)(Ab + o + 8);
        a[ks][3] = *(const uint32_t*)(Ab + o + 8 * ASTRIDE + 8);
    }

    float acc[16][4];
    #pragma unroll
    for (int nt = 0; nt < 16; nt++)
        #pragma unroll
        for (int q = 0; q < 4; q++) acc[nt][q] = 0.f;

    #pragma unroll
    for (int nt = 0; nt < 16; nt++) {
        const __nv_bfloat16* Bb = Bs + (nt * 8 + g) * ASTRIDE + 2 * t4;
        #pragma unroll
        for (int ks = 0; ks < 8; ks++) {
            uint32_t b0 = *(const uint32_t*)(Bb + ks * 16);
            uint32_t b1 = *(const uint32_t*)(Bb + ks * 16 + 8);
            asm volatile(
                "mma.sync.aligned.m16n8k16.row.col.f32.bf16.bf16.f32 "
                "{%0,%1,%2,%3}, {%4,%5,%6,%7}, {%8,%9}, {%0,%1,%2,%3};\n"
                : "+f"(acc[nt][0]), "+f"(acc[nt][1]),
                  "+f"(acc[nt][2]), "+f"(acc[nt][3])
                : "r"(a[ks][0]), "r"(a[ks][1]), "r"(a[ks][2]), "r"(a[ks][3]),
                  "r"(b0), "r"(b1));
        }
    }

    // Epilogue: + bias - xm[seg]; sector-aligned float2 stores
    int ra = r0 + m0 + g;
    int rb = ra + 8;
    int sa = seg[ra];
    int sb = seg[rb];
    const float* xa = g_xm + (size_t)sa * DIM;
    const float* xb = g_xm + (size_t)sb * DIM;

    #pragma unroll
    for (int nt = 0; nt < 16; nt++) {
        int j = nt * 8 + 2 * t4;
        float2 bb = *(const float2*)(bias + j);
        float2 ma = *(const float2*)(xa + j);
        float2 mb = *(const float2*)(xb + j);
        float2 oa, ob;
        oa.x = acc[nt][0] + bb.x - ma.x;
        oa.y = acc[nt][1] + bb.y - ma.y;
        ob.x = acc[nt][2] + bb.x - mb.x;
        ob.y = acc[nt][3] + bb.y - mb.y;
        *(float2*)(out + (size_t)ra * DIM + j) = oa;
        *(float2*)(out + (size_t)rb * DIM + j) = ob;
    }
}

// ---------------------------------------------------------------------------
extern "C" void kernel_launch(void* const* d_in, const int* in_sizes, int n_in,
                              void* d_out, int out_size) {
    const float* x   = (const float*)d_in[0];
    const int*   seg = (const int*)d_in[1];
    // Robustly locate Gamma_W (16384), Gamma_b (128), Lambda_W (16384)
    const float* GW = nullptr;
    const float* Gb = nullptr;
    const float* LW = nullptr;
    for (int i = 2; i < n_in; i++) {
        int s = in_sizes[i];
        if (s == DIM * DIM) { if (!GW) GW = (const float*)d_in[i]; else LW = (const float*)d_in[i]; }
        else if (s == DIM) { Gb = (const float*)d_in[i]; }
    }
    float* out = (float*)d_out;

    cudaFuncSetAttribute(k2_xm,   cudaFuncAttributeMaxDynamicSharedMemorySize, 74240);
    cudaFuncSetAttribute(k3_main, cudaFuncAttributeMaxDynamicSharedMemorySize, K3_SMEM);

    k0_init<<<2048, 256>>>(GW);
    k1_segsum<<<NROWS / 1024, 256>>>(x, seg);
    k2_xm<<<NSEG / 16, 128, 74240>>>(LW);
    k3_main<<<NROWS / 128, 256, K3_SMEM>>>(x, seg, Gb, out);
}

// round 3
// speedup vs baseline: 1.0106x; 1.0051x over previous
#include <cuda_runtime.h>
#include <cuda_bf16.h>
#include <cstdint>

// Problem constants (fixed by the dataset)
#define NROWS 1048576
#define DIM   128
#define NSEG  4096

// Scratch (allocation-free rule: __device__ globals)
__device__ float g_xs[NSEG * DIM];              // segment sums   (2 MB)
__device__ float g_xm[NSEG * DIM];              // xs @ Lambda^T  (2 MB)
__device__ __nv_bfloat16 g_Gb[DIM * DIM];       // Gamma_W in bf16 (32 KB)

// ---------------------------------------------------------------------------
// Kernel 0: zero g_xs, convert Gamma_W -> bf16
// ---------------------------------------------------------------------------
__global__ void k0_init(const float* __restrict__ GW) {
    int idx = blockIdx.x * blockDim.x + threadIdx.x;
    if (idx < NSEG * DIM) g_xs[idx] = 0.0f;
    if (idx < DIM * DIM)  g_Gb[idx] = __float2bfloat16(GW[idx]);
}

// ---------------------------------------------------------------------------
// Kernel 1: segment sum over sorted seg_ids.
// 256 threads = 8 row-streams of 32 lanes; each lane owns 4 columns (float4).
// Run-length accumulate in registers, atomicAdd only at segment boundaries.
// unroll 8 -> 8 independent (seg,x) loads in flight per stream.
// ---------------------------------------------------------------------------
__global__ __launch_bounds__(256) void k1_segsum(const float* __restrict__ x,
                                                 const int* __restrict__ seg) {
    int t = threadIdx.x;
    int stream = t >> 5;              // 0..7
    int c = (t & 31) * 4;             // column base
    int base = blockIdx.x * 1024 + stream;

    float4 acc = make_float4(0.f, 0.f, 0.f, 0.f);
    int cur = seg[base];

    #pragma unroll 8
    for (int i = 0; i < 128; i++) {
        int r = base + i * 8;
        int s = seg[r];
        float4 v = *(const float4*)(x + (size_t)r * DIM + c);
        if (s != cur) {
            float* d = g_xs + (size_t)cur * DIM + c;
            atomicAdd(d + 0, acc.x); atomicAdd(d + 1, acc.y);
            atomicAdd(d + 2, acc.z); atomicAdd(d + 3, acc.w);
            acc = make_float4(0.f, 0.f, 0.f, 0.f);
            cur = s;
        }
        acc.x += v.x; acc.y += v.y; acc.z += v.z; acc.w += v.w;
    }
    float* d = g_xs + (size_t)cur * DIM + c;
    atomicAdd(d + 0, acc.x); atomicAdd(d + 1, acc.y);
    atomicAdd(d + 2, acc.z); atomicAdd(d + 3, acc.w);
}

// ---------------------------------------------------------------------------
// Kernel 2: g_xm = g_xs @ Lambda_W^T   (fp32 exact; xm dominates |out|)
// ---------------------------------------------------------------------------
__global__ __launch_bounds__(128) void k2_xm(const float* __restrict__ LW) {
    extern __shared__ float sm2[];
    float* Lt  = sm2;                 // [128][129], Lt[k][j] = LW[j][k]
    float* xss = sm2 + 128 * 129;     // [16][128]
    int t = threadIdx.x;
    int R0 = blockIdx.x * 16;

    for (int i = 0; i < 128; i++) {
        int e = i * 128 + t;
        int j = e >> 7, k = e & 127;
        Lt[k * 129 + j] = LW[e];
    }
    for (int i = 0; i < 16; i++) {
        int e = i * 128 + t;
        int r = e >> 7, k = e & 127;
        xss[r * 128 + k] = g_xs[(size_t)(R0 + r) * DIM + k];
    }
    __syncthreads();

    int j = t;
    float acc[16];
    #pragma unroll
    for (int r = 0; r < 16; r++) acc[r] = 0.f;

    for (int k = 0; k < 128; k++) {
        float lv = Lt[k * 129 + j];
        #pragma unroll
        for (int r = 0; r < 16; r++) acc[r] += xss[r * 128 + k] * lv;
    }
    #pragma unroll
    for (int r = 0; r < 16; r++)
        g_xm[(size_t)(R0 + r) * DIM + j] = acc[r];
}

// ---------------------------------------------------------------------------
// Kernel 3: out = x @ Gamma^T (bf16 HMMA) + bias - xm[seg]
// Block tile 128x128, 256 threads, warp = 16 rows x 128 cols.
// All fragment loads via ldmatrix.x4 (512 B/warp/instr) -> 4x fewer smem
// instructions than scalar LDS.32. A staged per-warp (own 16 rows only).
// Pad stride 136 halves => 8 tile-row addresses land on distinct 16B phases
// (17*16B stride) -> LDSM conflict-free.
// ---------------------------------------------------------------------------
#define ASTRIDE 136
#define K3_SMEM (2 * 128 * ASTRIDE * 2)   // 69632 bytes

__global__ __launch_bounds__(256, 2) void k3_main(const float* __restrict__ x,
                                                  const int* __restrict__ seg,
                                                  const float* __restrict__ bias,
                                                  float* __restrict__ out) {
    extern __shared__ __nv_bfloat16 sm3[];
    __nv_bfloat16* Bs = sm3;                       // [128][136]  Bs[n][k]=Gamma[n][k]
    __nv_bfloat16* As = sm3 + 128 * ASTRIDE;       // [128][136]

    int tid  = threadIdx.x;
    int warp = tid >> 5;
    int lane = tid & 31;
    int r0 = blockIdx.x * 128;
    int m0 = warp * 16;

    // Stage B (Gamma, pre-converted bf16; L2-resident) -- cooperative
    #pragma unroll
    for (int i = 0; i < 8; i++) {
        int e = i * 2048 + tid * 8;       // < 16384
        int r = e >> 7, c = e & 127;
        *(uint4*)(Bs + r * ASTRIDE + c) = *(const uint4*)(g_Gb + e);
    }

    // Stage A per-warp: warp converts its own 16 rows (512B-contiguous LDG.128s)
    #pragma unroll
    for (int i = 0; i < 16; i++) {
        int r = m0 + i;
        float4 v = *(const float4*)(x + (size_t)(r0 + r) * DIM + lane * 4);
        __nv_bfloat162* dst = (__nv_bfloat162*)(As + r * ASTRIDE + lane * 4);
        dst[0] = __floats2bfloat162_rn(v.x, v.y);
        dst[1] = __floats2bfloat162_rn(v.z, v.w);
    }

    // Prefetch epilogue segment ids while loads drain
    int g  = lane >> 2;                // 0..7
    int t4 = lane & 3;                 // 0..3
    int ra = r0 + m0 + g;
    int rb = ra + 8;
    int sa = seg[ra];
    int sb = seg[rb];

    __syncthreads();

    // A fragments: ldmatrix.x4, one per k-step (8 total, back-to-back)
    uint32_t a[8][4];
    {
        const __nv_bfloat16* ap =
            As + (m0 + (lane & 15)) * ASTRIDE + ((lane >> 4) << 3);
        #pragma unroll
        for (int ks = 0; ks < 8; ks++) {
            uint32_t addr = (uint32_t)__cvta_generic_to_shared(ap + ks * 16);
            asm volatile(
                "ldmatrix.sync.aligned.m8n8.x4.shared.b16 {%0,%1,%2,%3}, [%4];"
                : "=r"(a[ks][0]), "=r"(a[ks][1]), "=r"(a[ks][2]), "=r"(a[ks][3])
                : "r"(addr));
        }
    }

    float acc[16][4];
    #pragma unroll
    for (int nt = 0; nt < 16; nt++)
        #pragma unroll
        for (int q = 0; q < 4; q++) acc[nt][q] = 0.f;

    // B fragments: ldmatrix.x4 delivers (b0,b1) for TWO adjacent n-tiles at one ks
    const __nv_bfloat16* bp =
        Bs + ((lane & 7) + ((lane >> 4) << 3)) * ASTRIDE + (((lane >> 3) & 1) << 3);

    #pragma unroll
    for (int ntp = 0; ntp < 8; ntp++) {
        const __nv_bfloat16* bpp = bp + ntp * 16 * ASTRIDE;
        #pragma unroll
        for (int ks = 0; ks < 8; ks++) {
            uint32_t b0, b1, b2, b3;
            uint32_t addr = (uint32_t)__cvta_generic_to_shared(bpp + ks * 16);
            asm volatile(
                "ldmatrix.sync.aligned.m8n8.x4.shared.b16 {%0,%1,%2,%3}, [%4];"
                : "=r"(b0), "=r"(b1), "=r"(b2), "=r"(b3)
                : "r"(addr));
            asm volatile(
                "mma.sync.aligned.m16n8k16.row.col.f32.bf16.bf16.f32 "
                "{%0,%1,%2,%3}, {%4,%5,%6,%7}, {%8,%9}, {%0,%1,%2,%3};\n"
                : "+f"(acc[2 * ntp][0]), "+f"(acc[2 * ntp][1]),
                  "+f"(acc[2 * ntp][2]), "+f"(acc[2 * ntp][3])
                : "r"(a[ks][0]), "r"(a[ks][1]), "r"(a[ks][2]), "r"(a[ks][3]),
                  "r"(b0), "r"(b1));
            asm volatile(
                "mma.sync.aligned.m16n8k16.row.col.f32.bf16.bf16.f32 "
                "{%0,%1,%2,%3}, {%4,%5,%6,%7}, {%8,%9}, {%0,%1,%2,%3};\n"
                : "+f"(acc[2 * ntp + 1][0]), "+f"(acc[2 * ntp + 1][1]),
                  "+f"(acc[2 * ntp + 1][2]), "+f"(acc[2 * ntp + 1][3])
                : "r"(a[ks][0]), "r"(a[ks][1]), "r"(a[ks][2]), "r"(a[ks][3]),
                  "r"(b2), "r"(b3));
        }
    }

    // Epilogue: + bias - xm[seg]; sector-aligned float2 stores
    const float* xa = g_xm + (size_t)sa * DIM;
    const float* xb = g_xm + (size_t)sb * DIM;

    #pragma unroll
    for (int nt = 0; nt < 16; nt++) {
        int j = nt * 8 + 2 * t4;
        float2 bb = *(const float2*)(bias + j);
        float2 ma = *(const float2*)(xa + j);
        float2 mb = *(const float2*)(xb + j);
        float2 oa, ob;
        oa.x = acc[nt][0] + bb.x - ma.x;
        oa.y = acc[nt][1] + bb.y - ma.y;
        ob.x = acc[nt][2] + bb.x - mb.x;
        ob.y = acc[nt][3] + bb.y - mb.y;
        *(float2*)(out + (size_t)ra * DIM + j) = oa;
        *(float2*)(out + (size_t)rb * DIM + j) = ob;
    }
}

// ---------------------------------------------------------------------------
extern "C" void kernel_launch(void* const* d_in, const int* in_sizes, int n_in,
                              void* d_out, int out_size) {
    const float* x   = (const float*)d_in[0];
    const int*   seg = (const int*)d_in[1];
    const float* GW = nullptr;
    const float* Gb = nullptr;
    const float* LW = nullptr;
    for (int i = 2; i < n_in; i++) {
        int s = in_sizes[i];
        if (s == DIM * DIM) { if (!GW) GW = (const float*)d_in[i]; else LW = (const float*)d_in[i]; }
        else if (s == DIM) { Gb = (const float*)d_in[i]; }
    }
    float* out = (float*)d_out;

    cudaFuncSetAttribute(k2_xm,   cudaFuncAttributeMaxDynamicSharedMemorySize, 74240);
    cudaFuncSetAttribute(k3_main, cudaFuncAttributeMaxDynamicSharedMemorySize, K3_SMEM);

    k0_init<<<2048, 256>>>(GW);
    k1_segsum<<<NROWS / 1024, 256>>>(x, seg);
    k2_xm<<<NSEG / 16, 128, 74240>>>(LW);
    k3_main<<<NROWS / 128, 256, K3_SMEM>>>(x, seg, Gb, out);
}